// round 14
// baseline (speedup 1.0000x reference)
#include <cuda_runtime.h>
#include <cstdint>

#define B_DIM 16
#define C_DIM 256
#define N_DIM 16384
#define K_DIM 8
#define NB 32
#define NT 512                   // tiles per b
#define GR 27                    // blocks per b -> 432 blocks (~3/SM, single wave)
#define NSTAGES 10
#define KAPPA 20.0f

// ---- smem (floats), single x buffer ----
// x: [256 c][36] stride-36 (16B-aligned rows for cp.async; p1 col reads conflict-free)
#define XS 36
#define XSLOT (C_DIM * XS)                 // 9216
#define MU_OFF XSLOT                       // 9216
#define MU_SIZE (C_DIM * K_DIM)            // 2048
#define PART_OFF (MU_OFF + MU_SIZE)        // 11264 ; [16 w][272] xor-swizzled
#define PART_SIZE (16 * 272)               // 4352
#define Z_OFF (PART_OFF + PART_SIZE)       // 15616 ; z[n*8 + 4*(n>>4) + k]
#define Z_SIZE 264
#define S_OFF (Z_OFF + Z_SIZE)             // 15880
#define SM_FLOATS (S_OFF + 8)              // 15888
#define SMEM_BYTES (SM_FLOATS * 4)         // 63552 B -> 3 blocks/SM

__device__ float g_mu[B_DIM * C_DIM * K_DIM];
__device__ float g_M [B_DIM * C_DIM * K_DIM];
__device__ float g_S [B_DIM * K_DIM];

__device__ __forceinline__ float2 ffma2(float2 a, float2 b, float2 c) {
    float2 d;
    asm("fma.rn.f32x2 %0, %1, %2, %3;"
        : "=l"(reinterpret_cast<unsigned long long&>(d))
        : "l"(reinterpret_cast<unsigned long long&>(a)),
          "l"(reinterpret_cast<unsigned long long&>(b)),
          "l"(reinterpret_cast<unsigned long long&>(c)));
    return d;
}

__device__ __forceinline__ void cp_async16(uint32_t dst, const float* src) {
    asm volatile("cp.async.cg.shared.global [%0], [%1], 16;" :: "r"(dst), "l"(src));
}

__global__ void init_kernel(const float* __restrict__ mu_in) {
    int idx = blockIdx.x * blockDim.x + threadIdx.x;
    if (idx < B_DIM * C_DIM * K_DIM) {
        g_mu[idx] = mu_in[idx & (C_DIM * K_DIM - 1)];
        g_M[idx]  = 0.0f;
    }
    if (idx < B_DIM * K_DIM) g_S[idx] = 0.0f;
}

__global__ __launch_bounds__(512, 3)
void em_stage(const float* __restrict__ x, int last, float* __restrict__ z_out) {
    extern __shared__ float sm[];
    float* s_mu   = sm + MU_OFF;
    float* s_part = sm + PART_OFF;
    float* s_z    = sm + Z_OFF;
    float* s_S    = sm + S_OFF;

    uint32_t smb;
    asm("{ .reg .u64 t; cvta.to.shared.u64 t, %1; cvt.u32.u64 %0, t; }"
        : "=r"(smb) : "l"(sm));

    const int tid  = threadIdx.x;
    const int warp = tid >> 5, lane = tid & 31;
    const int b    = blockIdx.y;
    const float* xb = x + (size_t)b * C_DIM * N_DIM;

    // p2 mapping: c = tid>>1, n-half = tid&1   (R10 mapping)
    const int lc = tid >> 1, lh = tid & 1;

    // reduce mapping: 2 threads per (n,k)
    const int rw = tid & 1, rk = (tid >> 1) & 7, rn = tid >> 4;

    #pragma unroll
    for (int it = 0; it < 4; ++it) {
        int i = it * 512 + tid;
        s_mu[i] = g_mu[b * (C_DIM * K_DIM) + i];
    }
    if (tid < 8) s_S[tid] = 0.0f;

    float2 M0 = {0.f,0.f}, M1 = {0.f,0.f}, M2 = {0.f,0.f}, M3 = {0.f,0.f};
    float Sacc = 0.0f;

    // contiguous tile range for this block: [tbeg, tend)
    const int tbeg = (blockIdx.x * NT) / GR;
    const int tend = ((blockIdx.x + 1) * NT) / GR;

    // ---- prologue: fill buffer with tile tbeg ----
    #pragma unroll
    for (int it = 0; it < 4; ++it) {
        int ci = it * 512 + tid;
        int c  = ci >> 3, q = ci & 7;
        cp_async16(smb + (c * XS + q * 4) * 4,
                   xb + (size_t)c * N_DIM + (size_t)tbeg * NB + q * 4);
    }
    asm volatile("cp.async.commit_group;" ::: "memory");

    for (int t = tbeg; t < tend; ++t) {
        asm volatile("cp.async.wait_group 0;" ::: "memory");
        __syncthreads();                       // fill visible to all

        // ===== phase 1: c-slice 16 per warp, lane = n =====
        {
            float2 A0={0.f,0.f},A1={0.f,0.f},A2={0.f,0.f},A3={0.f,0.f};
            const float*  xp = sm + warp * (16 * XS) + lane;
            const float4* mp = (const float4*)(s_mu + warp * 128);
            #pragma unroll
            for (int i = 0; i < 16; ++i) {
                float  xv = xp[i * XS];
                float2 xs = make_float2(xv, xv);
                float4 m0 = mp[2*i], m1 = mp[2*i+1];     // broadcast
                A0 = ffma2(xs, make_float2(m0.x, m0.y), A0);
                A1 = ffma2(xs, make_float2(m0.z, m0.w), A1);
                A2 = ffma2(xs, make_float2(m1.x, m1.y), A2);
                A3 = ffma2(xs, make_float2(m1.z, m1.w), A3);
            }
            int sw = (lane >> 2) & 7;
            float* pb = s_part + warp * 272 + lane * 8;
            pb[0^sw]=A0.x; pb[1^sw]=A0.y; pb[2^sw]=A1.x; pb[3^sw]=A1.y;
            pb[4^sw]=A2.x; pb[5^sw]=A2.y; pb[6^sw]=A3.x; pb[7^sw]=A3.y;
        }
        __syncthreads();                       // part visible; p1 x reads done

        // ---- copy this thread's p2 x-row to registers (frees buffer for refill) ----
        float4 r0, r1, r2, r3;
        {
            const float* xr = sm + lc * XS + lh * 16;
            r0 = *(const float4*)(xr + 0);  r1 = *(const float4*)(xr + 4);
            r2 = *(const float4*)(xr + 8);  r3 = *(const float4*)(xr + 12);
        }

        // ===== reduce over 16 c-slices + softmax =====
        {
            int col = rn * 8 + (rk ^ ((rn >> 2) & 7));
            float v = 0.f;
            #pragma unroll
            for (int i = 0; i < 8; ++i)
                v += s_part[(rw + 2*i) * 272 + col];
            v += __shfl_xor_sync(~0u, v, 1);
            v *= KAPPA;
            float mx = v;
            mx = fmaxf(mx, __shfl_xor_sync(~0u, mx, 2));
            mx = fmaxf(mx, __shfl_xor_sync(~0u, mx, 4));
            mx = fmaxf(mx, __shfl_xor_sync(~0u, mx, 8));
            float e = __expf(v - mx);
            float s = e;
            s += __shfl_xor_sync(~0u, s, 2);
            s += __shfl_xor_sync(~0u, s, 4);
            s += __shfl_xor_sync(~0u, s, 8);
            float z = e / s;
            if (rw == 0) {
                s_z[rn * 8 + ((rn >> 4) << 2) + rk] = z;
                Sacc += z;
                if (last)
                    z_out[(((size_t)b * N_DIM + (size_t)t * NB + rn) << 3) + rk] = z;
            }
        }
        __syncthreads();                       // x-row copies done, z visible

        // ---- buffer free: start fill for tile t+1 (overlaps phase-2 FMA) ----
        if (t + 1 < tend) {
            #pragma unroll
            for (int it = 0; it < 4; ++it) {
                int ci = it * 512 + tid;
                int c  = ci >> 3, q = ci & 7;
                cp_async16(smb + (c * XS + q * 4) * 4,
                           xb + (size_t)c * N_DIM + (size_t)(t + 1) * NB + q * 4);
            }
        }
        asm volatile("cp.async.commit_group;" ::: "memory");

        // ===== phase 2: x from registers, z broadcast from smem =====
        {
            const float* zr = s_z + lh * 132;
            float xv[16] = {r0.x,r0.y,r0.z,r0.w, r1.x,r1.y,r1.z,r1.w,
                            r2.x,r2.y,r2.z,r2.w, r3.x,r3.y,r3.z,r3.w};
            #pragma unroll
            for (int jj = 0; jj < 16; ++jj) {
                float2 xs = make_float2(xv[jj], xv[jj]);
                float4 za = *(const float4*)(zr + 8*jj);
                float4 zb = *(const float4*)(zr + 8*jj + 4);
                M0 = ffma2(xs, make_float2(za.x, za.y), M0);
                M1 = ffma2(xs, make_float2(za.z, za.w), M1);
                M2 = ffma2(xs, make_float2(zb.x, zb.y), M2);
                M3 = ffma2(xs, make_float2(zb.z, zb.w), M3);
            }
        }
        // no bottom sync: next-top wait+sync is the boundary; s_z is only
        // rewritten after the NEXT post-p1 and post-reduce syncs.
    }

    // ---- epilogue: merge lh pairs, flush M and S ----
    M0.x += __shfl_xor_sync(~0u, M0.x, 1);  M0.y += __shfl_xor_sync(~0u, M0.y, 1);
    M1.x += __shfl_xor_sync(~0u, M1.x, 1);  M1.y += __shfl_xor_sync(~0u, M1.y, 1);
    M2.x += __shfl_xor_sync(~0u, M2.x, 1);  M2.y += __shfl_xor_sync(~0u, M2.y, 1);
    M3.x += __shfl_xor_sync(~0u, M3.x, 1);  M3.y += __shfl_xor_sync(~0u, M3.y, 1);
    if (lh == 0) {
        float* Mp = g_M + ((size_t)b * C_DIM + lc) * K_DIM;
        atomicAdd(Mp + 0, M0.x); atomicAdd(Mp + 1, M0.y);
        atomicAdd(Mp + 2, M1.x); atomicAdd(Mp + 3, M1.y);
        atomicAdd(Mp + 4, M2.x); atomicAdd(Mp + 5, M2.y);
        atomicAdd(Mp + 6, M3.x); atomicAdd(Mp + 7, M3.y);
    }
    Sacc += __shfl_xor_sync(~0u, Sacc, 16);
    Sacc += __shfl_xor_sync(~0u, Sacc, 1);
    if ((lane & 0x11) == 0) atomicAdd(s_S + rk, Sacc);
    __syncthreads();
    if (tid < 8) atomicAdd(g_S + b * K_DIM + tid, s_S[tid]);
}

__global__ void finalize_kernel(int last, float* __restrict__ mu_out) {
    const int k = blockIdx.x;
    const int b = blockIdx.y;
    const int c = threadIdx.x;
    __shared__ float red[256];

    float S = g_S[b * K_DIM + k];
    float val = g_M[((size_t)b * C_DIM + c) * K_DIM + k] / (1e-6f + S);

    red[c] = val * val;
    __syncthreads();
    for (int s = 128; s > 0; s >>= 1) {
        if (c < s) red[c] += red[c + s];
        __syncthreads();
    }
    float m = val / (1e-6f + sqrtf(red[0]));

    g_mu[((size_t)b * C_DIM + c) * K_DIM + k] = m;
    g_M [((size_t)b * C_DIM + c) * K_DIM + k] = 0.0f;
    if (c == 0) g_S[b * K_DIM + k] = 0.0f;
    if (last) mu_out[((size_t)b * K_DIM + k) * C_DIM + c] = m;
}

__global__ void zdiv_kernel(float* __restrict__ z) {
    int idx = blockIdx.x * blockDim.x + threadIdx.x;
    if (idx < B_DIM * N_DIM * K_DIM) {
        int k = idx & 7;
        int b = idx >> 17;
        z[idx] = z[idx] / (1e-6f + g_S[b * K_DIM + k]);
    }
}

extern "C" void kernel_launch(void* const* d_in, const int* in_sizes, int n_in,
                              void* d_out, int out_size) {
    const float* x     = (const float*)d_in[0];
    const float* mu_in = (const float*)d_in[1];
    float* out    = (float*)d_out;
    float* mu_out = out;
    float* z_out  = out + B_DIM * K_DIM * C_DIM;

    cudaFuncSetAttribute(em_stage, cudaFuncAttributeMaxDynamicSharedMemorySize, SMEM_BYTES);

    init_kernel<<<128, 256>>>(mu_in);
    for (int s = 0; s < NSTAGES; ++s) {
        int last = (s == NSTAGES - 1);
        em_stage<<<dim3(GR, B_DIM), 512, SMEM_BYTES>>>(x, last, z_out);
        if (last) zdiv_kernel<<<(B_DIM * N_DIM * K_DIM) / 256, 256>>>(z_out);
        finalize_kernel<<<dim3(K_DIM, B_DIM), 256>>>(last, mu_out);
    }
}

// round 15
// speedup vs baseline: 1.0420x; 1.0420x over previous
#include <cuda_runtime.h>
#include <cstdint>

#define B_DIM 16
#define C_DIM 256
#define N_DIM 16384
#define K_DIM 8
#define NB 32
#define NT 512                   // tiles per b
#define GR 18                    // blocks per b -> 288 blocks (~2/SM, single wave)
#define NSTAGES 10
#define KAPPA 20.0f

// ---- smem (floats), DOUBLE x buffer ----
// x slot: [256 c][36] stride-36 (16B-aligned rows for cp.async; p1 col reads conflict-free)
#define XS 36
#define XSLOT (C_DIM * XS)                 // 9216
#define MU_OFF (2 * XSLOT)                 // 18432
#define MU_SIZE (C_DIM * K_DIM)            // 2048
#define PART_OFF (MU_OFF + MU_SIZE)        // 20480 ; [16 w][272] xor-swizzled
#define PART_SIZE (16 * 272)               // 4352
#define Z_OFF (PART_OFF + PART_SIZE)       // 24832 ; z[n*8 + 4*(n>>4) + k]
#define Z_SIZE 264
#define S_OFF (Z_OFF + Z_SIZE)             // 25096
#define SM_FLOATS (S_OFF + 8)              // 25104
#define SMEM_BYTES (SM_FLOATS * 4)         // 100416 B -> 2 blocks/SM

__device__ float g_mu[B_DIM * C_DIM * K_DIM];
__device__ float g_M [B_DIM * C_DIM * K_DIM];
__device__ float g_S [B_DIM * K_DIM];

__device__ __forceinline__ float2 ffma2(float2 a, float2 b, float2 c) {
    float2 d;
    asm("fma.rn.f32x2 %0, %1, %2, %3;"
        : "=l"(reinterpret_cast<unsigned long long&>(d))
        : "l"(reinterpret_cast<unsigned long long&>(a)),
          "l"(reinterpret_cast<unsigned long long&>(b)),
          "l"(reinterpret_cast<unsigned long long&>(c)));
    return d;
}

__device__ __forceinline__ void cp_async16(uint32_t dst, const float* src) {
    asm volatile("cp.async.cg.shared.global [%0], [%1], 16;" :: "r"(dst), "l"(src));
}

__global__ void init_kernel(const float* __restrict__ mu_in) {
    int idx = blockIdx.x * blockDim.x + threadIdx.x;
    if (idx < B_DIM * C_DIM * K_DIM) {
        g_mu[idx] = mu_in[idx & (C_DIM * K_DIM - 1)];
        g_M[idx]  = 0.0f;
    }
    if (idx < B_DIM * K_DIM) g_S[idx] = 0.0f;
}

__global__ __launch_bounds__(512, 2)
void em_stage(const float* __restrict__ x, int last, float* __restrict__ z_out) {
    extern __shared__ float sm[];
    float* s_mu   = sm + MU_OFF;
    float* s_part = sm + PART_OFF;
    float* s_z    = sm + Z_OFF;
    float* s_S    = sm + S_OFF;

    uint32_t smb;
    asm("{ .reg .u64 t; cvta.to.shared.u64 t, %1; cvt.u32.u64 %0, t; }"
        : "=r"(smb) : "l"(sm));

    const int tid  = threadIdx.x;
    const int warp = tid >> 5, lane = tid & 31;
    const int b    = blockIdx.y;
    const float* xb = x + (size_t)b * C_DIM * N_DIM;

    // p2 mapping: c = tid>>1, n-half = tid&1   (R10 mapping)
    const int lc = tid >> 1, lh = tid & 1;

    // reduce mapping: 2 threads per (n,k)
    const int rw = tid & 1, rk = (tid >> 1) & 7, rn = tid >> 4;

    #pragma unroll
    for (int it = 0; it < 4; ++it) {
        int i = it * 512 + tid;
        s_mu[i] = g_mu[b * (C_DIM * K_DIM) + i];
    }
    if (tid < 8) s_S[tid] = 0.0f;

    float2 M0 = {0.f,0.f}, M1 = {0.f,0.f}, M2 = {0.f,0.f}, M3 = {0.f,0.f};
    float Sacc = 0.0f;

    const int t0 = blockIdx.x;

    // ---- prologue: fill slot 0 with tile t0 ----
    #pragma unroll
    for (int it = 0; it < 4; ++it) {
        int ci = it * 512 + tid;
        int c  = ci >> 3, q = ci & 7;
        cp_async16(smb + (c * XS + q * 4) * 4,
                   xb + (size_t)c * N_DIM + (size_t)t0 * NB + q * 4);
    }
    asm volatile("cp.async.commit_group;" ::: "memory");

    int cur = 0;
    for (int t = t0; t < NT; t += GR) {
        // ---- TOP: issue fill for tile t+GR into the OTHER slot (full-iter distance) ----
        if (t + GR < NT) {
            uint32_t slotb = smb + (cur ^ 1) * (XSLOT * 4);
            #pragma unroll
            for (int it = 0; it < 4; ++it) {
                int ci = it * 512 + tid;
                int c  = ci >> 3, q = ci & 7;
                cp_async16(slotb + (c * XS + q * 4) * 4,
                           xb + (size_t)c * N_DIM + (size_t)(t + GR) * NB + q * 4);
            }
        }
        asm volatile("cp.async.commit_group;" ::: "memory");

        // wait for THIS tile's fill (allow the just-issued one to stay in flight)
        asm volatile("cp.async.wait_group 1;" ::: "memory");
        __syncthreads();                       // fill visible to all

        const float* sx = sm + cur * XSLOT;

        // ===== phase 1: c-slice 16 per warp, lane = n =====
        {
            float2 A0={0.f,0.f},A1={0.f,0.f},A2={0.f,0.f},A3={0.f,0.f};
            const float*  xp = sx + warp * (16 * XS) + lane;
            const float4* mp = (const float4*)(s_mu + warp * 128);
            #pragma unroll
            for (int i = 0; i < 16; ++i) {
                float  xv = xp[i * XS];
                float2 xs = make_float2(xv, xv);
                float4 m0 = mp[2*i], m1 = mp[2*i+1];     // broadcast
                A0 = ffma2(xs, make_float2(m0.x, m0.y), A0);
                A1 = ffma2(xs, make_float2(m0.z, m0.w), A1);
                A2 = ffma2(xs, make_float2(m1.x, m1.y), A2);
                A3 = ffma2(xs, make_float2(m1.z, m1.w), A3);
            }
            int sw = (lane >> 2) & 7;
            float* pb = s_part + warp * 272 + lane * 8;
            pb[0^sw]=A0.x; pb[1^sw]=A0.y; pb[2^sw]=A1.x; pb[3^sw]=A1.y;
            pb[4^sw]=A2.x; pb[5^sw]=A2.y; pb[6^sw]=A3.x; pb[7^sw]=A3.y;
        }
        __syncthreads();                       // part visible; p1 x reads done

        // ---- copy this thread's p2 x-row to registers ----
        float4 r0, r1, r2, r3;
        {
            const float* xr = sx + lc * XS + lh * 16;
            r0 = *(const float4*)(xr + 0);  r1 = *(const float4*)(xr + 4);
            r2 = *(const float4*)(xr + 8);  r3 = *(const float4*)(xr + 12);
        }

        // ===== reduce over 16 c-slices + softmax =====
        {
            int col = rn * 8 + (rk ^ ((rn >> 2) & 7));
            float v = 0.f;
            #pragma unroll
            for (int i = 0; i < 8; ++i)
                v += s_part[(rw + 2*i) * 272 + col];
            v += __shfl_xor_sync(~0u, v, 1);
            v *= KAPPA;
            float mx = v;
            mx = fmaxf(mx, __shfl_xor_sync(~0u, mx, 2));
            mx = fmaxf(mx, __shfl_xor_sync(~0u, mx, 4));
            mx = fmaxf(mx, __shfl_xor_sync(~0u, mx, 8));
            float e = __expf(v - mx);
            float s = e;
            s += __shfl_xor_sync(~0u, s, 2);
            s += __shfl_xor_sync(~0u, s, 4);
            s += __shfl_xor_sync(~0u, s, 8);
            float z = e / s;
            if (rw == 0) {
                s_z[rn * 8 + ((rn >> 4) << 2) + rk] = z;
                Sacc += z;
                if (last)
                    z_out[(((size_t)b * N_DIM + (size_t)t * NB + rn) << 3) + rk] = z;
            }
        }
        __syncthreads();                       // x-row copies done, z visible

        // ===== phase 2: x from registers, z broadcast from smem =====
        {
            const float* zr = s_z + lh * 132;
            float xv[16] = {r0.x,r0.y,r0.z,r0.w, r1.x,r1.y,r1.z,r1.w,
                            r2.x,r2.y,r2.z,r2.w, r3.x,r3.y,r3.z,r3.w};
            #pragma unroll
            for (int jj = 0; jj < 16; ++jj) {
                float2 xs = make_float2(xv[jj], xv[jj]);
                float4 za = *(const float4*)(zr + 8*jj);
                float4 zb = *(const float4*)(zr + 8*jj + 4);
                M0 = ffma2(xs, make_float2(za.x, za.y), M0);
                M1 = ffma2(xs, make_float2(za.z, za.w), M1);
                M2 = ffma2(xs, make_float2(zb.x, zb.y), M2);
                M3 = ffma2(xs, make_float2(zb.z, zb.w), M3);
            }
        }
        cur ^= 1;
        // no bottom sync: next-top wait+sync is the boundary; s_z is only
        // rewritten after the NEXT post-p1 and post-reduce syncs, and the
        // next fill targets the slot this iteration consumed (freed by then).
    }

    // ---- epilogue: merge lh pairs, flush M and S ----
    M0.x += __shfl_xor_sync(~0u, M0.x, 1);  M0.y += __shfl_xor_sync(~0u, M0.y, 1);
    M1.x += __shfl_xor_sync(~0u, M1.x, 1);  M1.y += __shfl_xor_sync(~0u, M1.y, 1);
    M2.x += __shfl_xor_sync(~0u, M2.x, 1);  M2.y += __shfl_xor_sync(~0u, M2.y, 1);
    M3.x += __shfl_xor_sync(~0u, M3.x, 1);  M3.y += __shfl_xor_sync(~0u, M3.y, 1);
    if (lh == 0) {
        float* Mp = g_M + ((size_t)b * C_DIM + lc) * K_DIM;
        atomicAdd(Mp + 0, M0.x); atomicAdd(Mp + 1, M0.y);
        atomicAdd(Mp + 2, M1.x); atomicAdd(Mp + 3, M1.y);
        atomicAdd(Mp + 4, M2.x); atomicAdd(Mp + 5, M2.y);
        atomicAdd(Mp + 6, M3.x); atomicAdd(Mp + 7, M3.y);
    }
    Sacc += __shfl_xor_sync(~0u, Sacc, 16);
    Sacc += __shfl_xor_sync(~0u, Sacc, 1);
    if ((lane & 0x11) == 0) atomicAdd(s_S + rk, Sacc);
    __syncthreads();
    if (tid < 8) atomicAdd(g_S + b * K_DIM + tid, s_S[tid]);
}

__global__ void finalize_kernel(int last, float* __restrict__ mu_out) {
    const int k = blockIdx.x;
    const int b = blockIdx.y;
    const int c = threadIdx.x;
    __shared__ float red[256];

    float S = g_S[b * K_DIM + k];
    float val = g_M[((size_t)b * C_DIM + c) * K_DIM + k] / (1e-6f + S);

    red[c] = val * val;
    __syncthreads();
    for (int s = 128; s > 0; s >>= 1) {
        if (c < s) red[c] += red[c + s];
        __syncthreads();
    }
    float m = val / (1e-6f + sqrtf(red[0]));

    g_mu[((size_t)b * C_DIM + c) * K_DIM + k] = m;
    g_M [((size_t)b * C_DIM + c) * K_DIM + k] = 0.0f;
    if (c == 0) g_S[b * K_DIM + k] = 0.0f;
    if (last) mu_out[((size_t)b * K_DIM + k) * C_DIM + c] = m;
}

__global__ void zdiv_kernel(float* __restrict__ z) {
    int idx = blockIdx.x * blockDim.x + threadIdx.x;
    if (idx < B_DIM * N_DIM * K_DIM) {
        int k = idx & 7;
        int b = idx >> 17;
        z[idx] = z[idx] / (1e-6f + g_S[b * K_DIM + k]);
    }
}

extern "C" void kernel_launch(void* const* d_in, const int* in_sizes, int n_in,
                              void* d_out, int out_size) {
    const float* x     = (const float*)d_in[0];
    const float* mu_in = (const float*)d_in[1];
    float* out    = (float*)d_out;
    float* mu_out = out;
    float* z_out  = out + B_DIM * K_DIM * C_DIM;

    cudaFuncSetAttribute(em_stage, cudaFuncAttributeMaxDynamicSharedMemorySize, SMEM_BYTES);

    init_kernel<<<128, 256>>>(mu_in);
    for (int s = 0; s < NSTAGES; ++s) {
        int last = (s == NSTAGES - 1);
        em_stage<<<dim3(GR, B_DIM), 512, SMEM_BYTES>>>(x, last, z_out);
        if (last) zdiv_kernel<<<(B_DIM * N_DIM * K_DIM) / 256, 256>>>(z_out);
        finalize_kernel<<<dim3(K_DIM, B_DIM), 256>>>(last, mu_out);
    }
}

// round 17
// speedup vs baseline: 1.0763x; 1.0329x over previous
#include <cuda_runtime.h>
#include <cstdint>

#define B_DIM 16
#define C_DIM 256
#define N_DIM 16384
#define K_DIM 8
#define NB 32
#define NT 512                   // tiles per b
#define GR 27                    // blocks per b -> 432 blocks (~3/SM, single wave)
#define NSTAGES 10
#define KAPPA 20.0f

// ---- smem (floats), single x buffer, warp-owned regions ----
// x: [256 c][36] stride-36 (16B-aligned rows; p1 col reads conflict-free)
// warp w owns rows c in [16w, 16w+16)
#define XS 36
#define XSLOT (C_DIM * XS)                 // 9216
#define MU_OFF XSLOT                       // 9216
#define MU_SIZE (C_DIM * K_DIM)            // 2048
#define PART_OFF (MU_OFF + MU_SIZE)        // 11264 ; [16 w][272] xor-swizzled
#define PART_SIZE (16 * 272)               // 4352
#define Z_OFF (PART_OFF + PART_SIZE)       // 15616 ; z[n*8 + 4*(n>>4) + k]
#define Z_SIZE 264
#define S_OFF (Z_OFF + Z_SIZE)             // 15880
#define SM_FLOATS (S_OFF + 8)              // 15888
#define SMEM_BYTES (SM_FLOATS * 4)         // 63552 B -> 3 blocks/SM

__device__ float g_mu[B_DIM * C_DIM * K_DIM];
__device__ float g_M [B_DIM * C_DIM * K_DIM];
__device__ float g_S [B_DIM * K_DIM];

__device__ __forceinline__ float2 ffma2(float2 a, float2 b, float2 c) {
    float2 d;
    asm("fma.rn.f32x2 %0, %1, %2, %3;"
        : "=l"(reinterpret_cast<unsigned long long&>(d))
        : "l"(reinterpret_cast<unsigned long long&>(a)),
          "l"(reinterpret_cast<unsigned long long&>(b)),
          "l"(reinterpret_cast<unsigned long long&>(c)));
    return d;
}

__device__ __forceinline__ void cp_async16(uint32_t dst, const float* src) {
    asm volatile("cp.async.cg.shared.global [%0], [%1], 16;" :: "r"(dst), "l"(src));
}

__global__ void init_kernel(const float* __restrict__ mu_in) {
    int idx = blockIdx.x * blockDim.x + threadIdx.x;
    if (idx < B_DIM * C_DIM * K_DIM) {
        g_mu[idx] = mu_in[idx & (C_DIM * K_DIM - 1)];
        g_M[idx]  = 0.0f;
    }
    if (idx < B_DIM * K_DIM) g_S[idx] = 0.0f;
}

__global__ __launch_bounds__(512, 3)
void em_stage(const float* __restrict__ x, int last, float* __restrict__ z_out) {
    extern __shared__ float sm[];
    float* s_mu   = sm + MU_OFF;
    float* s_part = sm + PART_OFF;
    float* s_z    = sm + Z_OFF;
    float* s_S    = sm + S_OFF;

    uint32_t smb;
    asm("{ .reg .u64 t; cvta.to.shared.u64 t, %1; cvt.u32.u64 %0, t; }"
        : "=r"(smb) : "l"(sm));

    const int tid  = threadIdx.x;
    const int warp = tid >> 5, lane = tid & 31;
    const int b    = blockIdx.y;
    const float* xb = x + (size_t)b * C_DIM * N_DIM;

    // p2 mapping: c = tid>>1, n-half = tid&1
    const int lc = tid >> 1, lh = tid & 1;

    // reduce mapping: 2 threads per (n,k)
    const int rw = tid & 1, rk = (tid >> 1) & 7, rn = tid >> 4;

    // per-warp fill: warp fills its OWN region rows [16*warp, 16*warp+16)
    const int wrow0 = warp << 4;

    #pragma unroll
    for (int it = 0; it < 4; ++it) {
        int i = it * 512 + tid;
        s_mu[i] = g_mu[b * (C_DIM * K_DIM) + i];
    }
    if (tid < 8) s_S[tid] = 0.0f;

    float2 M0 = {0.f,0.f}, M1 = {0.f,0.f}, M2 = {0.f,0.f}, M3 = {0.f,0.f};
    float Sacc = 0.0f;

    const int t0 = blockIdx.x;

    // ---- prologue: each warp fills its own region with tile t0 ----
    #pragma unroll
    for (int it = 0; it < 4; ++it) {
        int ci = it * 32 + lane;                 // 128 chunks per region
        int r  = ci >> 3, q = ci & 7;
        cp_async16(smb + ((wrow0 + r) * XS + q * 4) * 4,
                   xb + (size_t)(wrow0 + r) * N_DIM + (size_t)t0 * NB + q * 4);
    }
    asm volatile("cp.async.commit_group;" ::: "memory");
    __syncthreads();   // order prologue s_mu / s_S writes before ANY warp's p1

    for (int t = t0; t < NT; t += GR) {
        // per-warp: wait only for OUR region's fill, then go
        asm volatile("cp.async.wait_group 0;" ::: "memory");
        __syncwarp();

        // ===== phase 1: c-slice 16 per warp (own region), lane = n =====
        {
            float2 A0={0.f,0.f},A1={0.f,0.f},A2={0.f,0.f},A3={0.f,0.f};
            const float*  xp = sm + wrow0 * XS + lane;
            const float4* mp = (const float4*)(s_mu + warp * 128);
            #pragma unroll
            for (int i = 0; i < 16; ++i) {
                float  xv = xp[i * XS];
                float2 xs = make_float2(xv, xv);
                float4 m0 = mp[2*i], m1 = mp[2*i+1];     // broadcast
                A0 = ffma2(xs, make_float2(m0.x, m0.y), A0);
                A1 = ffma2(xs, make_float2(m0.z, m0.w), A1);
                A2 = ffma2(xs, make_float2(m1.x, m1.y), A2);
                A3 = ffma2(xs, make_float2(m1.z, m1.w), A3);
            }
            int sw = (lane >> 2) & 7;
            float* pb = s_part + warp * 272 + lane * 8;
            pb[0^sw]=A0.x; pb[1^sw]=A0.y; pb[2^sw]=A1.x; pb[3^sw]=A1.y;
            pb[4^sw]=A2.x; pb[5^sw]=A2.y; pb[6^sw]=A3.x; pb[7^sw]=A3.y;
        }
        __syncthreads();   // sync2: part + ALL warps' fills visible block-wide

        // ---- copy this thread's p2 x-row to registers (cross-warp read OK) ----
        float4 r0, r1, r2, r3;
        {
            const float* xr = sm + lc * XS + lh * 16;
            r0 = *(const float4*)(xr + 0);  r1 = *(const float4*)(xr + 4);
            r2 = *(const float4*)(xr + 8);  r3 = *(const float4*)(xr + 12);
        }

        // ===== reduce over 16 c-slices + softmax =====
        {
            int col = rn * 8 + (rk ^ ((rn >> 2) & 7));
            float v = 0.f;
            #pragma unroll
            for (int i = 0; i < 8; ++i)
                v += s_part[(rw + 2*i) * 272 + col];
            v += __shfl_xor_sync(~0u, v, 1);
            v *= KAPPA;
            float mx = v;
            mx = fmaxf(mx, __shfl_xor_sync(~0u, mx, 2));
            mx = fmaxf(mx, __shfl_xor_sync(~0u, mx, 4));
            mx = fmaxf(mx, __shfl_xor_sync(~0u, mx, 8));
            float e = __expf(v - mx);
            float s = e;
            s += __shfl_xor_sync(~0u, s, 2);
            s += __shfl_xor_sync(~0u, s, 4);
            s += __shfl_xor_sync(~0u, s, 8);
            float z = e / s;
            if (rw == 0) {
                s_z[rn * 8 + ((rn >> 4) << 2) + rk] = z;
                Sacc += z;
                if (last)
                    z_out[(((size_t)b * N_DIM + (size_t)t * NB + rn) << 3) + rk] = z;
            }
        }
        __syncthreads();   // sync3: x-row copies done, z visible

        // ---- region free: refill OUR region for tile t+GR (overlaps p2) ----
        if (t + GR < NT) {
            #pragma unroll
            for (int it = 0; it < 4; ++it) {
                int ci = it * 32 + lane;
                int r  = ci >> 3, q = ci & 7;
                cp_async16(smb + ((wrow0 + r) * XS + q * 4) * 4,
                           xb + (size_t)(wrow0 + r) * N_DIM + (size_t)(t + GR) * NB + q * 4);
            }
        }
        asm volatile("cp.async.commit_group;" ::: "memory");

        // ===== phase 2: x from registers, z broadcast from smem =====
        {
            const float* zr = s_z + lh * 132;
            float xv[16] = {r0.x,r0.y,r0.z,r0.w, r1.x,r1.y,r1.z,r1.w,
                            r2.x,r2.y,r2.z,r2.w, r3.x,r3.y,r3.z,r3.w};
            #pragma unroll
            for (int jj = 0; jj < 16; ++jj) {
                float2 xs = make_float2(xv[jj], xv[jj]);
                float4 za = *(const float4*)(zr + 8*jj);
                float4 zb = *(const float4*)(zr + 8*jj + 4);
                M0 = ffma2(xs, make_float2(za.x, za.y), M0);
                M1 = ffma2(xs, make_float2(za.z, za.w), M1);
                M2 = ffma2(xs, make_float2(zb.x, zb.y), M2);
                M3 = ffma2(xs, make_float2(zb.z, zb.w), M3);
            }
        }
        // loop top: per-warp wait on own refill; s_part rewrite is after this
        // iteration's sync3 (all reduces done); s_z rewrite after next sync2
        // (all p2 done) — ordering safe with 2 block barriers per tile.
    }

    // ---- epilogue: merge lh pairs, flush M and S ----
    M0.x += __shfl_xor_sync(~0u, M0.x, 1);  M0.y += __shfl_xor_sync(~0u, M0.y, 1);
    M1.x += __shfl_xor_sync(~0u, M1.x, 1);  M1.y += __shfl_xor_sync(~0u, M1.y, 1);
    M2.x += __shfl_xor_sync(~0u, M2.x, 1);  M2.y += __shfl_xor_sync(~0u, M2.y, 1);
    M3.x += __shfl_xor_sync(~0u, M3.x, 1);  M3.y += __shfl_xor_sync(~0u, M3.y, 1);
    if (lh == 0) {
        float* Mp = g_M + ((size_t)b * C_DIM + lc) * K_DIM;
        atomicAdd(Mp + 0, M0.x); atomicAdd(Mp + 1, M0.y);
        atomicAdd(Mp + 2, M1.x); atomicAdd(Mp + 3, M1.y);
        atomicAdd(Mp + 4, M2.x); atomicAdd(Mp + 5, M2.y);
        atomicAdd(Mp + 6, M3.x); atomicAdd(Mp + 7, M3.y);
    }
    Sacc += __shfl_xor_sync(~0u, Sacc, 16);
    Sacc += __shfl_xor_sync(~0u, Sacc, 1);
    if ((lane & 0x11) == 0) atomicAdd(s_S + rk, Sacc);
    __syncthreads();
    if (tid < 8) atomicAdd(g_S + b * K_DIM + tid, s_S[tid]);
}

__global__ void finalize_kernel(int last, float* __restrict__ mu_out) {
    const int k = blockIdx.x;
    const int b = blockIdx.y;
    const int c = threadIdx.x;
    __shared__ float red[256];

    float S = g_S[b * K_DIM + k];
    float val = g_M[((size_t)b * C_DIM + c) * K_DIM + k] / (1e-6f + S);

    red[c] = val * val;
    __syncthreads();
    for (int s = 128; s > 0; s >>= 1) {
        if (c < s) red[c] += red[c + s];
        __syncthreads();
    }
    float m = val / (1e-6f + sqrtf(red[0]));

    g_mu[((size_t)b * C_DIM + c) * K_DIM + k] = m;
    g_M [((size_t)b * C_DIM + c) * K_DIM + k] = 0.0f;
    if (c == 0) g_S[b * K_DIM + k] = 0.0f;
    if (last) mu_out[((size_t)b * K_DIM + k) * C_DIM + c] = m;
}

__global__ void zdiv_kernel(float* __restrict__ z) {
    int idx = blockIdx.x * blockDim.x + threadIdx.x;
    if (idx < B_DIM * N_DIM * K_DIM) {
        int k = idx & 7;
        int b = idx >> 17;
        z[idx] = z[idx] / (1e-6f + g_S[b * K_DIM + k]);
    }
}

extern "C" void kernel_launch(void* const* d_in, const int* in_sizes, int n_in,
                              void* d_out, int out_size) {
    const float* x     = (const float*)d_in[0];
    const float* mu_in = (const float*)d_in[1];
    float* out    = (float*)d_out;
    float* mu_out = out;
    float* z_out  = out + B_DIM * K_DIM * C_DIM;

    cudaFuncSetAttribute(em_stage, cudaFuncAttributeMaxDynamicSharedMemorySize, SMEM_BYTES);

    init_kernel<<<128, 256>>>(mu_in);
    for (int s = 0; s < NSTAGES; ++s) {
        int last = (s == NSTAGES - 1);
        em_stage<<<dim3(GR, B_DIM), 512, SMEM_BYTES>>>(x, last, z_out);
        if (last) zdiv_kernel<<<(B_DIM * N_DIM * K_DIM) / 256, 256>>>(z_out);
        finalize_kernel<<<dim3(K_DIM, B_DIM), 256>>>(last, mu_out);
    }
}